// round 1
// baseline (speedup 1.0000x reference)
#include <cuda_runtime.h>
#include <math.h>

#define Bb 64
#define Tt 64
#define INDIM 64
#define CDIM 256
#define NN 1024
#define MV 64
#define OUTDIM 64
#define NT 1024
#define EPSF 1e-8f

// 16 MB scratch for memory matrix M[B][N][MV] (device global: allocation-free)
__device__ float g_M[(size_t)Bb * NN * MV];

__device__ __forceinline__ float sigmoidf_(float x) { return 1.f / (1.f + expf(-x)); }
__device__ __forceinline__ float softplusf_(float x) { return (x > 20.f) ? x : log1pf(expf(x)); }

struct __align__(16) Smem {
    float dotb[NN];        // per-row dot with key
    float ssb[NN];         // per-row sum of squares
    float wcarry[NN];      // carried weights (w_prev for write head; w_r after read)
    float ww[NN];          // write-head weights
    float wtmp[NN];        // w_g buffer for circular shift
    float scratch[2048];   // GEMV partials / read-vector partials
    float c[CDIM];
    float cat[INDIM + MV];
    float hw[224];         // 198 used
    float hr[96];          // 70 used
    float kw[MV], kr[MV], ev[MV], av[MV], rv[MV];
    float red[32];
    float sc[16];          // scalars: 0..5 write(beta,g,s0,s1,s2,gamma), 6 knorm_w,
                           // 7..12 read(beta,g,s0,s1,s2,gamma), 13 knorm_r
};

__device__ __forceinline__ float blockReduce(float v, bool isMax, float* red, int tid) {
    #pragma unroll
    for (int off = 16; off; off >>= 1) {
        float o = __shfl_xor_sync(0xffffffffu, v, off);
        v = isMax ? fmaxf(v, o) : (v + o);
    }
    if ((tid & 31) == 0) red[tid >> 5] = v;
    __syncthreads();
    if (tid < 32) {
        float x = red[tid];
        #pragma unroll
        for (int off = 16; off; off >>= 1) {
            float o = __shfl_xor_sync(0xffffffffu, x, off);
            x = isMax ? fmaxf(x, o) : (x + o);
        }
        if (tid == 0) red[0] = x;
    }
    __syncthreads();
    float res = red[0];
    __syncthreads();
    return res;
}

// Content addressing + interpolation + shift + sharpen. dotb/ssb already hold
// per-row dot(M,k) and sumsq(M). Produces wout[tid].
__device__ __forceinline__ void addressFn(int tid, Smem& s, const float* wprev, float* wout,
                                          float knorm, float beta, float gg,
                                          float s0, float s1, float s2, float gamma) {
    float sim = beta * s.dotb[tid] / (sqrtf(s.ssb[tid]) * knorm + EPSF);
    float mx = blockReduce(sim, true, s.red, tid);
    float p = expf(sim - mx);
    float Z = blockReduce(p, false, s.red, tid);
    float wg = gg * (p / Z) + (1.f - gg) * wprev[tid];
    s.wtmp[tid] = wg;
    __syncthreads();
    // roll(w,-1)[n]=w[n+1]; roll(w,+1)[n]=w[n-1]; s=(s_-1, s_0, s_+1)
    float ws = s0 * s.wtmp[(tid + 1) & (NN - 1)] + s1 * s.wtmp[tid] + s2 * s.wtmp[(tid - 1) & (NN - 1)];
    float wp = powf(ws + EPSF, gamma);
    float S = blockReduce(wp, false, s.red, tid);
    wout[tid] = wp / S;
    __syncthreads();
}

__global__ __launch_bounds__(NT, 1)
void ntm_kernel(const float* __restrict__ x,
                const float* __restrict__ Wc, const float* __restrict__ bc,
                const float* __restrict__ Wr, const float* __restrict__ br,
                const float* __restrict__ Ww, const float* __restrict__ bw,
                const float* __restrict__ Wf, const float* __restrict__ bf,
                const float* __restrict__ r_bias, const float* __restrict__ w_bias,
                const float* __restrict__ M_bias, float* __restrict__ out) {
    __shared__ Smem s;
    const int tid = threadIdx.x;
    const int b = blockIdx.x;
    const int wid = tid >> 5, lane = tid & 31;
    const int half = lane >> 4, sub = lane & 15;
    float4* Mb4 = (float4*)(g_M + (size_t)b * NN * MV);

    // ---- init state (every launch: deterministic) ----
    for (int i = tid; i < NN * MV / 4; i += NT) Mb4[i] = ((const float4*)M_bias)[i];
    for (int i = tid; i < NN; i += NT) s.wcarry[i] = w_bias[i];
    if (tid < MV) s.rv[tid] = r_bias[tid];
    __syncthreads();

    for (int t = 0; t < Tt; ++t) {
        // ---- concat(x_t, r) ----
        if (tid < INDIM) s.cat[tid] = x[((size_t)b * Tt + t) * INDIM + tid];
        else if (tid < INDIM + MV) s.cat[tid] = s.rv[tid - INDIM];
        __syncthreads();

        // ---- controller: c = tanh(cat @ Wc + bc)  [128 x 256] ----
        {
            int g = tid >> 8, i = tid & 255;
            float acc = 0.f;
            int j0 = g * 32;
            #pragma unroll
            for (int j = 0; j < 32; ++j) acc = fmaf(s.cat[j0 + j], Wc[(j0 + j) * CDIM + i], acc);
            s.scratch[g * 256 + i] = acc;
        }
        __syncthreads();
        if (tid < CDIM)
            s.c[tid] = tanhf(s.scratch[tid] + s.scratch[256 + tid] + s.scratch[512 + tid] +
                             s.scratch[768 + tid] + bc[tid]);
        __syncthreads();

        // ---- hw = c @ Ww + bw  [256 x 198] ----
        {
            int g = tid >> 8, i = tid & 255;
            float acc = 0.f;
            if (i < 198) {
                int j0 = g * 64;
                #pragma unroll
                for (int j = 0; j < 64; ++j) acc = fmaf(s.c[j0 + j], Ww[(j0 + j) * 198 + i], acc);
            }
            s.scratch[g * 256 + i] = acc;
        }
        __syncthreads();
        if (tid < 198)
            s.hw[tid] = s.scratch[tid] + s.scratch[256 + tid] + s.scratch[512 + tid] +
                        s.scratch[768 + tid] + bw[tid];
        __syncthreads();

        // ---- hr = c @ Wr + br  [256 x 70] ----
        {
            int g = tid >> 8, i = tid & 255;
            float acc = 0.f;
            if (i < 70) {
                int j0 = g * 64;
                #pragma unroll
                for (int j = 0; j < 64; ++j) acc = fmaf(s.c[j0 + j], Wr[(j0 + j) * 70 + i], acc);
            }
            s.scratch[g * 256 + i] = acc;
        }
        __syncthreads();
        if (tid < 70)
            s.hr[tid] = s.scratch[tid] + s.scratch[256 + tid] + s.scratch[512 + tid] +
                        s.scratch[768 + tid] + br[tid];
        __syncthreads();

        // ---- head parameter transforms (both heads in parallel) ----
        if (tid < 64) s.kw[tid] = tanhf(s.hw[tid]);
        else if (tid < 128) s.kr[tid - 64] = tanhf(s.hr[tid - 64]);
        else if (tid < 192) s.ev[tid - 128] = sigmoidf_(s.hw[70 + tid - 128]);
        else if (tid < 256) s.av[tid - 192] = tanhf(s.hw[134 + tid - 192]);
        else if (tid == 256) s.sc[0] = softplusf_(s.hw[64]);
        else if (tid == 257) s.sc[1] = sigmoidf_(s.hw[65]);
        else if (tid == 258) {
            float a0 = s.hw[66], a1 = s.hw[67], a2 = s.hw[68];
            float m = fmaxf(a0, fmaxf(a1, a2));
            float e0 = expf(a0 - m), e1 = expf(a1 - m), e2 = expf(a2 - m);
            float z = e0 + e1 + e2;
            s.sc[2] = e0 / z; s.sc[3] = e1 / z; s.sc[4] = e2 / z;
        }
        else if (tid == 259) s.sc[5] = 1.f + softplusf_(s.hw[69]);
        else if (tid == 260) s.sc[7] = softplusf_(s.hr[64]);
        else if (tid == 261) s.sc[8] = sigmoidf_(s.hr[65]);
        else if (tid == 262) {
            float a0 = s.hr[66], a1 = s.hr[67], a2 = s.hr[68];
            float m = fmaxf(a0, fmaxf(a1, a2));
            float e0 = expf(a0 - m), e1 = expf(a1 - m), e2 = expf(a2 - m);
            float z = e0 + e1 + e2;
            s.sc[9] = e0 / z; s.sc[10] = e1 / z; s.sc[11] = e2 / z;
        }
        else if (tid == 263) s.sc[12] = 1.f + softplusf_(s.hr[69]);
        __syncthreads();

        // ---- key norms ----
        {
            float kv = 0.f;
            if (tid < 64) { float v = s.kw[tid]; kv = v * v; }
            else if (tid < 128) { float v = s.kr[tid - 64]; kv = v * v; }
            #pragma unroll
            for (int off = 16; off; off >>= 1) kv += __shfl_xor_sync(0xffffffffu, kv, off);
            if (lane == 0 && wid < 4) s.red[wid] = kv;
            __syncthreads();
            if (tid == 0) s.sc[6] = sqrtf(s.red[0] + s.red[1]);
            if (tid == 1) s.sc[13] = sqrtf(s.red[2] + s.red[3]);
            __syncthreads();
        }

        // ---- Pass A: dot(M, k_w) and sumsq per row ----
        // warp wid owns rows [wid*32, wid*32+32); half-warp per row, float4 per lane
        {
            float4 kk = *(const float4*)(s.kw + 4 * sub);
            #pragma unroll 4
            for (int n0 = 0; n0 < 32; n0 += 2) {
                int n = (wid << 5) + n0 + half;
                float4 m = Mb4[n * 16 + sub];
                float d = m.x * kk.x + m.y * kk.y + m.z * kk.z + m.w * kk.w;
                float q = m.x * m.x + m.y * m.y + m.z * m.z + m.w * m.w;
                #pragma unroll
                for (int off = 8; off; off >>= 1) {
                    d += __shfl_xor_sync(0xffffffffu, d, off);
                    q += __shfl_xor_sync(0xffffffffu, q, off);
                }
                if (sub == 0) { s.dotb[n] = d; s.ssb[n] = q; }
            }
        }
        __syncthreads();

        // ---- write-head addressing: w_prev = wcarry -> ww ----
        addressFn(tid, s, s.wcarry, s.ww, s.sc[6], s.sc[0], s.sc[1],
                  s.sc[2], s.sc[3], s.sc[4], s.sc[5]);

        // ---- Pass B: M update (erase/add) fused with dot(M', k_r) + sumsq ----
        {
            float4 kk = *(const float4*)(s.kr + 4 * sub);
            float4 ee = *(const float4*)(s.ev + 4 * sub);
            float4 aa = *(const float4*)(s.av + 4 * sub);
            #pragma unroll 4
            for (int n0 = 0; n0 < 32; n0 += 2) {
                int n = (wid << 5) + n0 + half;
                float wn = s.ww[n];
                float4 m = Mb4[n * 16 + sub];
                m.x = m.x * (1.f - wn * ee.x) + wn * aa.x;
                m.y = m.y * (1.f - wn * ee.y) + wn * aa.y;
                m.z = m.z * (1.f - wn * ee.z) + wn * aa.z;
                m.w = m.w * (1.f - wn * ee.w) + wn * aa.w;
                Mb4[n * 16 + sub] = m;
                float d = m.x * kk.x + m.y * kk.y + m.z * kk.z + m.w * kk.w;
                float q = m.x * m.x + m.y * m.y + m.z * m.z + m.w * m.w;
                #pragma unroll
                for (int off = 8; off; off >>= 1) {
                    d += __shfl_xor_sync(0xffffffffu, d, off);
                    q += __shfl_xor_sync(0xffffffffu, q, off);
                }
                if (sub == 0) { s.dotb[n] = d; s.ssb[n] = q; }
            }
        }
        __syncthreads();

        // ---- read-head addressing: w_prev = ww -> wcarry (= w_r) ----
        addressFn(tid, s, s.ww, s.wcarry, s.sc[13], s.sc[7], s.sc[8],
                  s.sc[9], s.sc[10], s.sc[11], s.sc[12]);

        // ---- Pass C: r = sum_n w_r[n] * M'[n] ----
        {
            float4 acc = make_float4(0.f, 0.f, 0.f, 0.f);
            #pragma unroll 4
            for (int n0 = 0; n0 < 32; n0 += 2) {
                int n = (wid << 5) + n0 + half;
                float wn = s.wcarry[n];
                float4 m = Mb4[n * 16 + sub];
                acc.x = fmaf(wn, m.x, acc.x);
                acc.y = fmaf(wn, m.y, acc.y);
                acc.z = fmaf(wn, m.z, acc.z);
                acc.w = fmaf(wn, m.w, acc.w);
            }
            acc.x += __shfl_xor_sync(0xffffffffu, acc.x, 16);
            acc.y += __shfl_xor_sync(0xffffffffu, acc.y, 16);
            acc.z += __shfl_xor_sync(0xffffffffu, acc.z, 16);
            acc.w += __shfl_xor_sync(0xffffffffu, acc.w, 16);
            if (half == 0) *(float4*)(s.scratch + wid * 64 + 4 * sub) = acc;
        }
        __syncthreads();
        if (tid < MV) {
            float acc = 0.f;
            #pragma unroll
            for (int w = 0; w < 32; ++w) acc += s.scratch[w * 64 + tid];
            s.rv[tid] = acc;
        }
        __syncthreads();

        // ---- out = sigmoid([c, r] @ Wf + bf)  [320 x 64] ----
        if (tid < 512) {
            int g = tid >> 6, o = tid & 63;
            float acc = 0.f;
            int j0 = g * 40;
            #pragma unroll
            for (int jj = 0; jj < 40; ++jj) {
                int j = j0 + jj;
                float v = (j < 256) ? s.c[j] : s.rv[j - 256];
                acc = fmaf(v, Wf[j * 64 + o], acc);
            }
            s.scratch[tid] = acc;
        }
        __syncthreads();
        if (tid < OUTDIM) {
            float acc = bf[tid];
            #pragma unroll
            for (int g = 0; g < 8; ++g) acc += s.scratch[g * 64 + tid];
            out[((size_t)b * Tt + t) * OUTDIM + tid] = sigmoidf_(acc);
        }
        __syncthreads();
    }
}

extern "C" void kernel_launch(void* const* d_in, const int* in_sizes, int n_in,
                              void* d_out, int out_size) {
    (void)in_sizes; (void)n_in; (void)out_size;
    ntm_kernel<<<Bb, NT>>>(
        (const float*)d_in[0],   // x
        (const float*)d_in[1],   // Wc
        (const float*)d_in[2],   // bc
        (const float*)d_in[3],   // Wr
        (const float*)d_in[4],   // br
        (const float*)d_in[5],   // Ww
        (const float*)d_in[6],   // bw
        (const float*)d_in[7],   // Wf
        (const float*)d_in[8],   // bf
        (const float*)d_in[9],   // r_bias
        (const float*)d_in[10],  // w_bias
        (const float*)d_in[11],  // M_bias
        (float*)d_out);
}

// round 2
// speedup vs baseline: 1.2440x; 1.2440x over previous
#include <cuda_runtime.h>
#include <math.h>

#define Tt 64
#define NT 512
#define SMS 520
#define EPSF 1e-8f

struct __align__(16) Smem {
    float Msm[64 * SMS];      // M rows 512..1023, column-major: Msm[j*SMS + r]
    float dotb[1024];
    float ssb[1024];
    float wcarry[1024];       // previous read weights (w_prev for write head)
    float ww[1024];           // write-head weights
    float wtmp[1024];
    float scratch[1024];
    float c[256];
    float cat[128];
    float hwv[200];           // 198 used
    float hrv[72];            // 70 used
    float kw[64], kr[64], ev[64], av[64], rv[64];
    float redA[16], redB[16], red2[8], sc[16];
};

__device__ __forceinline__ float sigmoidf_(float x) { return 1.f / (1.f + expf(-x)); }
__device__ __forceinline__ float softplusf_(float x) { return (x > 20.f) ? x : log1pf(expf(x)); }

__device__ __forceinline__ float bred(float v, bool isMax, float* red, int lane, int wid) {
    #pragma unroll
    for (int o = 16; o; o >>= 1) {
        float t = __shfl_xor_sync(0xffffffffu, v, o);
        v = isMax ? fmaxf(v, t) : (v + t);
    }
    if (lane == 0) red[wid] = v;
    __syncthreads();
    if (wid == 0) {
        float x = (lane < 16) ? red[lane] : (isMax ? -3.4e38f : 0.f);
        #pragma unroll
        for (int o = 8; o; o >>= 1) {
            float t = __shfl_xor_sync(0xffffffffu, x, o);
            x = isMax ? fmaxf(x, t) : (x + t);
        }
        if (lane == 0) red[0] = x;
    }
    __syncthreads();
    return red[0];
}

// Addressing for 2 rows per thread (n0=tid, n1=tid+512). dotb/ssb pre-filled.
__device__ __forceinline__ void addr2(int tid, int lane, int wid, Smem& s,
                                      const float* __restrict__ wprev, float* __restrict__ wout,
                                      float knorm, const float* scp,
                                      float* redA, float* redB) {
    const float beta = scp[0], g = scp[1], s0 = scp[2], s1 = scp[3], s2 = scp[4], gamma = scp[5];
    const int n0 = tid, n1 = tid + 512;
    float sim0 = beta * s.dotb[n0] / (sqrtf(s.ssb[n0]) * knorm + EPSF);
    float sim1 = beta * s.dotb[n1] / (sqrtf(s.ssb[n1]) * knorm + EPSF);
    float mx = bred(fmaxf(sim0, sim1), true, redA, lane, wid);
    float p0 = expf(sim0 - mx), p1 = expf(sim1 - mx);
    float Z = bred(p0 + p1, false, redB, lane, wid);
    float inv = 1.f / Z;
    float wg0 = g * p0 * inv + (1.f - g) * wprev[n0];
    float wg1 = g * p1 * inv + (1.f - g) * wprev[n1];
    s.wtmp[n0] = wg0; s.wtmp[n1] = wg1;
    __syncthreads();
    float ws0 = s0 * s.wtmp[(n0 + 1) & 1023] + s1 * wg0 + s2 * s.wtmp[(n0 - 1) & 1023];
    float ws1 = s0 * s.wtmp[(n1 + 1) & 1023] + s1 * wg1 + s2 * s.wtmp[(n1 - 1) & 1023];
    float wp0 = exp2f(gamma * log2f(ws0 + EPSF));
    float wp1 = exp2f(gamma * log2f(ws1 + EPSF));
    float S = bred(wp0 + wp1, false, redA, lane, wid);
    float invS = 1.f / S;
    wout[n0] = wp0 * invS; wout[n1] = wp1 * invS;
    __syncthreads();
}

__device__ __forceinline__ float head_dot(const Smem& s, const float* __restrict__ Ww,
                                          const float* __restrict__ Wr, int out, int half) {
    float acc = 0.f;
    const int j0 = half * 128;
    if (out < 198) {
        const float* w = Ww + (size_t)j0 * 198 + out;
        #pragma unroll 8
        for (int j = 0; j < 128; ++j) acc = fmaf(s.c[j0 + j], w[(size_t)j * 198], acc);
    } else {
        const float* w = Wr + (size_t)j0 * 70 + (out - 198);
        #pragma unroll 8
        for (int j = 0; j < 128; ++j) acc = fmaf(s.c[j0 + j], w[(size_t)j * 70], acc);
    }
    return acc;
}

__global__ __launch_bounds__(NT, 1)
void ntm_kernel(const float* __restrict__ x,
                const float* __restrict__ Wc, const float* __restrict__ bc,
                const float* __restrict__ Wr, const float* __restrict__ br,
                const float* __restrict__ Ww, const float* __restrict__ bw,
                const float* __restrict__ Wf, const float* __restrict__ bf,
                const float* __restrict__ r_bias, const float* __restrict__ w_bias,
                const float* __restrict__ M_bias, float* __restrict__ out) {
    extern __shared__ float smem_raw[];
    Smem& s = *reinterpret_cast<Smem*>(smem_raw);
    const int tid = threadIdx.x;
    const int lane = tid & 31, wid = tid >> 5;
    const int b = blockIdx.x;
    float Mreg[64];   // M row `tid`, resident in registers

    // ---- init state ----
    {
        float q = 0.f;
        const float* Mb = M_bias + (size_t)tid * 64;
        #pragma unroll
        for (int j = 0; j < 64; ++j) { float v = Mb[j]; Mreg[j] = v; q += v * v; }
        s.ssb[tid] = q;
        float q1 = 0.f;
        const float* Mb2 = M_bias + (size_t)(512 + tid) * 64;
        #pragma unroll 8
        for (int j = 0; j < 64; ++j) { float v = Mb2[j]; s.Msm[j * SMS + tid] = v; q1 += v * v; }
        s.ssb[512 + tid] = q1;
        s.wcarry[tid] = w_bias[tid];
        s.wcarry[512 + tid] = w_bias[512 + tid];
        if (tid < 64) s.rv[tid] = r_bias[tid];
    }
    __syncthreads();

    for (int t = 0; t < Tt; ++t) {
        // ---- concat(x_t, r) ----
        if (tid < 64) s.cat[tid] = x[((size_t)b * Tt + t) * 64 + tid];
        else if (tid < 128) s.cat[tid] = s.rv[tid - 64];
        __syncthreads();

        // ---- controller GEMV: c = tanh(cat @ Wc + bc), 256 outs x 2 K-halves ----
        {
            int o = tid & 255, half = tid >> 8;
            const float* w = Wc + (size_t)(half * 64) * 256 + o;
            float acc = 0.f;
            #pragma unroll 8
            for (int j = 0; j < 64; ++j) acc = fmaf(s.cat[half * 64 + j], w[(size_t)j * 256], acc);
            s.scratch[half * 256 + o] = acc;
        }
        __syncthreads();
        if (tid < 256) s.c[tid] = tanhf(s.scratch[tid] + s.scratch[256 + tid] + bc[tid]);
        __syncthreads();

        // ---- head GEMVs (hw: 198 outs, hr: 70 outs), 536 jobs over 512 threads ----
        {
            int o, half;
            if (tid < 268) { o = tid; half = 0; } else { o = tid - 268; half = 1; }
            s.scratch[half * 268 + o] = head_dot(s, Ww, Wr, o, half);
            if (tid < 24) {
                int o2 = 244 + tid;
                s.scratch[268 + o2] = head_dot(s, Ww, Wr, o2, 1);
            }
        }
        __syncthreads();
        if (tid < 268) {
            float v = s.scratch[tid] + s.scratch[268 + tid];
            if (tid < 198) s.hwv[tid] = v + bw[tid];
            else s.hrv[tid - 198] = v + br[tid - 198];
        }
        __syncthreads();

        // ---- head params + key-norm partials ----
        if (tid < 64) {
            float v = tanhf(s.hwv[tid]); s.kw[tid] = v;
            float q = v * v;
            #pragma unroll
            for (int o = 16; o; o >>= 1) q += __shfl_xor_sync(0xffffffffu, q, o);
            if (lane == 0) s.red2[wid] = q;                 // wid 0,1
        } else if (tid < 128) {
            float v = tanhf(s.hrv[tid - 64]); s.kr[tid - 64] = v;
            float q = v * v;
            #pragma unroll
            for (int o = 16; o; o >>= 1) q += __shfl_xor_sync(0xffffffffu, q, o);
            if (lane == 0) s.red2[wid] = q;                 // wid 2,3
        } else if (tid < 192) s.ev[tid - 128] = sigmoidf_(s.hwv[70 + tid - 128]);
        else if (tid < 256) s.av[tid - 192] = tanhf(s.hwv[134 + tid - 192]);
        else if (tid == 256) s.sc[0] = softplusf_(s.hwv[64]);
        else if (tid == 257) s.sc[1] = sigmoidf_(s.hwv[65]);
        else if (tid == 258) {
            float a0 = s.hwv[66], a1 = s.hwv[67], a2 = s.hwv[68];
            float m = fmaxf(a0, fmaxf(a1, a2));
            float e0 = expf(a0 - m), e1 = expf(a1 - m), e2 = expf(a2 - m);
            float z = e0 + e1 + e2;
            s.sc[2] = e0 / z; s.sc[3] = e1 / z; s.sc[4] = e2 / z;
        }
        else if (tid == 259) s.sc[5] = 1.f + softplusf_(s.hwv[69]);
        else if (tid == 260) s.sc[8] = softplusf_(s.hrv[64]);
        else if (tid == 261) s.sc[9] = sigmoidf_(s.hrv[65]);
        else if (tid == 262) {
            float a0 = s.hrv[66], a1 = s.hrv[67], a2 = s.hrv[68];
            float m = fmaxf(a0, fmaxf(a1, a2));
            float e0 = expf(a0 - m), e1 = expf(a1 - m), e2 = expf(a2 - m);
            float z = e0 + e1 + e2;
            s.sc[10] = e0 / z; s.sc[11] = e1 / z; s.sc[12] = e2 / z;
        }
        else if (tid == 263) s.sc[13] = 1.f + softplusf_(s.hrv[69]);
        __syncthreads();

        // ---- Pass A: dot(M, k_w) for both owned rows (sumsq reused from prev step) ----
        {
            float d0 = 0.f, d1 = 0.f;
            #pragma unroll
            for (int j4 = 0; j4 < 16; ++j4) {
                float4 kk = *(const float4*)(s.kw + 4 * j4);
                d0 += Mreg[4*j4] * kk.x + Mreg[4*j4+1] * kk.y + Mreg[4*j4+2] * kk.z + Mreg[4*j4+3] * kk.w;
                d1 += s.Msm[(4*j4  ) * SMS + tid] * kk.x + s.Msm[(4*j4+1) * SMS + tid] * kk.y
                    + s.Msm[(4*j4+2) * SMS + tid] * kk.z + s.Msm[(4*j4+3) * SMS + tid] * kk.w;
            }
            s.dotb[tid] = d0; s.dotb[512 + tid] = d1;
        }
        __syncthreads();

        // ---- write-head addressing ----
        {
            float knw = sqrtf(s.red2[0] + s.red2[1]);
            addr2(tid, lane, wid, s, s.wcarry, s.ww, knw, s.sc + 0, s.redA, s.redB);
        }

        // ---- Pass B: erase/add update + dot(M', k_r) + sumsq (both rows) ----
        {
            float w0 = s.ww[tid], w1 = s.ww[512 + tid];
            float d0 = 0.f, q0 = 0.f, d1 = 0.f, q1 = 0.f;
            #pragma unroll
            for (int j4 = 0; j4 < 16; ++j4) {
                float4 kk = *(const float4*)(s.kr + 4 * j4);
                float4 ee = *(const float4*)(s.ev + 4 * j4);
                float4 aa = *(const float4*)(s.av + 4 * j4);
                #pragma unroll
                for (int e = 0; e < 4; ++e) {
                    int j = 4 * j4 + e;
                    float ev_ = (e == 0) ? ee.x : (e == 1) ? ee.y : (e == 2) ? ee.z : ee.w;
                    float av_ = (e == 0) ? aa.x : (e == 1) ? aa.y : (e == 2) ? aa.z : aa.w;
                    float kv_ = (e == 0) ? kk.x : (e == 1) ? kk.y : (e == 2) ? kk.z : kk.w;
                    float mr = Mreg[j];
                    mr = mr * (1.f - w0 * ev_) + w0 * av_;
                    Mreg[j] = mr;
                    d0 = fmaf(mr, kv_, d0); q0 = fmaf(mr, mr, q0);
                    float ms = s.Msm[j * SMS + tid];
                    ms = ms * (1.f - w1 * ev_) + w1 * av_;
                    s.Msm[j * SMS + tid] = ms;
                    d1 = fmaf(ms, kv_, d1); q1 = fmaf(ms, ms, q1);
                }
            }
            s.dotb[tid] = d0; s.ssb[tid] = q0;
            s.dotb[512 + tid] = d1; s.ssb[512 + tid] = q1;
        }
        __syncthreads();

        // ---- read-head addressing (prev = ww) -> wcarry ----
        {
            float knr = sqrtf(s.red2[2] + s.red2[3]);
            addr2(tid, lane, wid, s, s.ww, s.wcarry, knr, s.sc + 8, s.redB, s.redA);
        }

        // ---- Pass C: r = sum_n w_r[n] * M[n]  (recursive-halving butterfly) ----
        {
            float wr0 = s.wcarry[tid], wr1 = s.wcarry[512 + tid];
            float A[32];
            bool up = (lane & 16);
            #pragma unroll
            for (int i = 0; i < 32; ++i) {
                float lo = wr0 * Mreg[i]      + wr1 * s.Msm[i * SMS + tid];
                float hi = wr0 * Mreg[i + 32] + wr1 * s.Msm[(i + 32) * SMS + tid];
                float keep = up ? hi : lo;
                float send = up ? lo : hi;
                A[i] = keep + __shfl_xor_sync(0xffffffffu, send, 16);
            }
            #pragma unroll
            for (int o = 8; o >= 1; o >>= 1) {
                int hl = o << 1;
                bool u2 = (lane & o);
                #pragma unroll
                for (int i = 0; i < 16; ++i) {
                    if (i < hl) {
                        float keep = u2 ? A[i + hl] : A[i];
                        float send = u2 ? A[i] : A[i + hl];
                        A[i] = keep + __shfl_xor_sync(0xffffffffu, send, o);
                    }
                }
            }
            // lane now holds elements 2*lane, 2*lane+1 summed over this warp's 64 rows
            s.scratch[wid * 64 + 2 * lane]     = A[0];
            s.scratch[wid * 64 + 2 * lane + 1] = A[1];
        }
        __syncthreads();
        if (tid < 64) {
            float acc = 0.f;
            #pragma unroll
            for (int w = 0; w < 16; ++w) acc += s.scratch[w * 64 + tid];
            s.rv[tid] = acc;
        }
        __syncthreads();

        // ---- out = sigmoid([c, r] @ Wf + bf): 64 outs x 8 K-segments of 40 ----
        {
            int o = tid & 63, seg = tid >> 6;
            int j0 = seg * 40;
            const float* w = Wf + (size_t)j0 * 64 + o;
            float acc = 0.f;
            #pragma unroll 8
            for (int jj = 0; jj < 40; ++jj) {
                int j = j0 + jj;
                float v = (j < 256) ? s.c[j] : s.rv[j - 256];
                acc = fmaf(v, w[(size_t)jj * 64], acc);
            }
            s.scratch[seg * 64 + o] = acc;
        }
        __syncthreads();
        if (tid < 64) {
            float acc = bf[tid];
            #pragma unroll
            for (int g = 0; g < 8; ++g) acc += s.scratch[g * 64 + tid];
            out[((size_t)b * Tt + t) * 64 + tid] = sigmoidf_(acc);
        }
        __syncthreads();
    }
}

extern "C" void kernel_launch(void* const* d_in, const int* in_sizes, int n_in,
                              void* d_out, int out_size) {
    (void)in_sizes; (void)n_in; (void)out_size;
    cudaFuncSetAttribute(ntm_kernel, cudaFuncAttributeMaxDynamicSharedMemorySize,
                         (int)sizeof(Smem));
    ntm_kernel<<<64, NT, sizeof(Smem)>>>(
        (const float*)d_in[0],   // x
        (const float*)d_in[1],   // Wc
        (const float*)d_in[2],   // bc
        (const float*)d_in[3],   // Wr
        (const float*)d_in[4],   // br
        (const float*)d_in[5],   // Ww
        (const float*)d_in[6],   // bw
        (const float*)d_in[7],   // Wf
        (const float*)d_in[8],   // bf
        (const float*)d_in[9],   // r_bias
        (const float*)d_in[10],  // w_bias
        (const float*)d_in[11],  // M_bias
        (float*)d_out);
}

// round 3
// speedup vs baseline: 1.7300x; 1.3907x over previous
#include <cuda_runtime.h>
#include <math.h>

#define Tt 64
#define NT 512
#define SMS 520
#define EPSF 1e-8f
#define HOUT 272   // padded head outputs: 198 (write) + 70 (read) + 4 pad

// Repacked fused head weights [256 K x 272 out], 16B-aligned rows (272 % 4 == 0)
__device__ __align__(16) float g_Wh[256 * HOUT];

struct __align__(16) Smem {
    float Msm[64 * SMS];      // M rows 512..1023, column-major: Msm[j*SMS + r]
    float dotb[1024];
    float ssb[1024];
    float wcarry[1024];
    float ww[1024];
    float wtmp[1024];
    float scratch[2176];      // GEMV partials (max 8*272) / Pass C partials
    float cr[320];            // concat(c, r) for final FC; cr[0..255] = c
    float cat[128];
    float hwv[200];           // 198 used
    float hrv[72];            // 70 used
    float kw[64], kr[64], ev[64], av[64], rv[64];
    float redA[16], redB[16], red2[8], sc[16];
};

__device__ __forceinline__ float sigmoidf_(float x) { return 1.f / (1.f + expf(-x)); }
__device__ __forceinline__ float softplusf_(float x) { return (x > 20.f) ? x : log1pf(expf(x)); }

__device__ __forceinline__ float bred(float v, bool isMax, float* red, int lane, int wid) {
    #pragma unroll
    for (int o = 16; o; o >>= 1) {
        float t = __shfl_xor_sync(0xffffffffu, v, o);
        v = isMax ? fmaxf(v, t) : (v + t);
    }
    if (lane == 0) red[wid] = v;
    __syncthreads();
    if (wid == 0) {
        float x = (lane < 16) ? red[lane] : (isMax ? -3.4e38f : 0.f);
        #pragma unroll
        for (int o = 8; o; o >>= 1) {
            float t = __shfl_xor_sync(0xffffffffu, x, o);
            x = isMax ? fmaxf(x, t) : (x + t);
        }
        if (lane == 0) red[0] = x;
    }
    __syncthreads();
    return red[0];
}

__device__ __forceinline__ void addr2(int tid, int lane, int wid, Smem& s,
                                      const float* __restrict__ wprev, float* __restrict__ wout,
                                      float knorm, const float* scp,
                                      float* redA, float* redB) {
    const float beta = scp[0], g = scp[1], s0 = scp[2], s1 = scp[3], s2 = scp[4], gamma = scp[5];
    const int n0 = tid, n1 = tid + 512;
    float sim0 = beta * s.dotb[n0] / (sqrtf(s.ssb[n0]) * knorm + EPSF);
    float sim1 = beta * s.dotb[n1] / (sqrtf(s.ssb[n1]) * knorm + EPSF);
    float mx = bred(fmaxf(sim0, sim1), true, redA, lane, wid);
    float p0 = expf(sim0 - mx), p1 = expf(sim1 - mx);
    float Z = bred(p0 + p1, false, redB, lane, wid);
    float inv = 1.f / Z;
    float wg0 = g * p0 * inv + (1.f - g) * wprev[n0];
    float wg1 = g * p1 * inv + (1.f - g) * wprev[n1];
    s.wtmp[n0] = wg0; s.wtmp[n1] = wg1;
    __syncthreads();
    float ws0 = s0 * s.wtmp[(n0 + 1) & 1023] + s1 * wg0 + s2 * s.wtmp[(n0 - 1) & 1023];
    float ws1 = s0 * s.wtmp[(n1 + 1) & 1023] + s1 * wg1 + s2 * s.wtmp[(n1 - 1) & 1023];
    float wp0 = exp2f(gamma * log2f(ws0 + EPSF));
    float wp1 = exp2f(gamma * log2f(ws1 + EPSF));
    float S = bred(wp0 + wp1, false, redA, lane, wid);
    float invS = 1.f / S;
    wout[n0] = wp0 * invS; wout[n1] = wp1 * invS;
    __syncthreads();
}

// Repack Ww [256,198] and Wr [256,70] into g_Wh [256,272] (pad cols 268..271 = 0)
__global__ void prep_kernel(const float* __restrict__ Ww, const float* __restrict__ Wr) {
    int j = blockIdx.x;         // 0..255 (K row)
    int t = threadIdx.x;        // 0..271
    float v = 0.f;
    if (t < 198) v = Ww[(size_t)j * 198 + t];
    else if (t < 268) v = Wr[(size_t)j * 70 + (t - 198)];
    g_Wh[(size_t)j * HOUT + t] = v;
}

__global__ __launch_bounds__(NT, 1)
void ntm_kernel(const float* __restrict__ x,
                const float* __restrict__ Wc, const float* __restrict__ bc,
                const float* __restrict__ br, const float* __restrict__ bw,
                const float* __restrict__ Wf, const float* __restrict__ bf,
                const float* __restrict__ r_bias, const float* __restrict__ w_bias,
                const float* __restrict__ M_bias, float* __restrict__ out) {
    extern __shared__ float smem_raw[];
    Smem& s = *reinterpret_cast<Smem*>(smem_raw);
    const int tid = threadIdx.x;
    const int lane = tid & 31, wid = tid >> 5;
    const int b = blockIdx.x;
    float Mreg[64];   // M row `tid` in registers

    // ---- init state ----
    {
        float q = 0.f;
        const float* Mb = M_bias + (size_t)tid * 64;
        #pragma unroll
        for (int j = 0; j < 64; ++j) { float v = Mb[j]; Mreg[j] = v; q += v * v; }
        s.ssb[tid] = q;
        float q1 = 0.f;
        const float* Mb2 = M_bias + (size_t)(512 + tid) * 64;
        #pragma unroll 8
        for (int j = 0; j < 64; ++j) { float v = Mb2[j]; s.Msm[j * SMS + tid] = v; q1 += v * v; }
        s.ssb[512 + tid] = q1;
        s.wcarry[tid] = w_bias[tid];
        s.wcarry[512 + tid] = w_bias[512 + tid];
        if (tid < 64) s.rv[tid] = r_bias[tid];
    }
    __syncthreads();

    for (int t = 0; t < Tt; ++t) {
        // ---- concat(x_t, r) ----
        if (tid < 64) s.cat[tid] = x[((size_t)b * Tt + t) * 64 + tid];
        else if (tid < 128) s.cat[tid] = s.rv[tid - 64];
        __syncthreads();

        // ---- controller GEMV: 64 out-groups(x4) x 8 K-splits(16) = 512 jobs ----
        {
            const int g = tid & 63, split = tid >> 6;
            const float4* w = (const float4*)(Wc) + (size_t)(split * 16) * 64 + g;
            float4 acc = make_float4(0.f, 0.f, 0.f, 0.f);
            #pragma unroll
            for (int j = 0; j < 16; ++j) {
                float v = s.cat[split * 16 + j];
                float4 w4 = w[(size_t)j * 64];
                acc.x = fmaf(v, w4.x, acc.x); acc.y = fmaf(v, w4.y, acc.y);
                acc.z = fmaf(v, w4.z, acc.z); acc.w = fmaf(v, w4.w, acc.w);
            }
            *(float4*)(s.scratch + split * 256 + 4 * g) = acc;
        }
        __syncthreads();
        if (tid < 256) {
            float acc = bc[tid];
            #pragma unroll
            for (int k = 0; k < 8; ++k) acc += s.scratch[k * 256 + tid];
            s.cr[tid] = tanhf(acc);
        }
        __syncthreads();

        // ---- head GEMV (fused hw+hr): 68 groups(x4) x 8 K-splits(32) ----
        {
            const int g = tid & 63, split = tid >> 6;
            const float4* w = (const float4*)(g_Wh) + (size_t)(split * 32) * (HOUT / 4) + g;
            float4 acc = make_float4(0.f, 0.f, 0.f, 0.f);
            #pragma unroll
            for (int j = 0; j < 32; ++j) {
                float v = s.cr[split * 32 + j];
                float4 w4 = w[(size_t)j * (HOUT / 4)];
                acc.x = fmaf(v, w4.x, acc.x); acc.y = fmaf(v, w4.y, acc.y);
                acc.z = fmaf(v, w4.z, acc.z); acc.w = fmaf(v, w4.w, acc.w);
            }
            *(float4*)(s.scratch + split * HOUT + 4 * g) = acc;
            if (tid < 32) {   // extra groups 64..67 (outs 256..271)
                const int g2 = 64 + (tid & 3), sp2 = tid >> 2;
                const float4* w2 = (const float4*)(g_Wh) + (size_t)(sp2 * 32) * (HOUT / 4) + g2;
                float4 a2 = make_float4(0.f, 0.f, 0.f, 0.f);
                #pragma unroll
                for (int j = 0; j < 32; ++j) {
                    float v = s.cr[sp2 * 32 + j];
                    float4 w4 = w2[(size_t)j * (HOUT / 4)];
                    a2.x = fmaf(v, w4.x, a2.x); a2.y = fmaf(v, w4.y, a2.y);
                    a2.z = fmaf(v, w4.z, a2.z); a2.w = fmaf(v, w4.w, a2.w);
                }
                *(float4*)(s.scratch + sp2 * HOUT + 4 * g2) = a2;
            }
        }
        __syncthreads();
        if (tid < 268) {
            float acc = 0.f;
            #pragma unroll
            for (int k = 0; k < 8; ++k) acc += s.scratch[k * HOUT + tid];
            if (tid < 198) s.hwv[tid] = acc + bw[tid];
            else s.hrv[tid - 198] = acc + br[tid - 198];
        }
        __syncthreads();

        // ---- head params + key-norm partials ----
        if (tid < 64) {
            float v = tanhf(s.hwv[tid]); s.kw[tid] = v;
            float q = v * v;
            #pragma unroll
            for (int o = 16; o; o >>= 1) q += __shfl_xor_sync(0xffffffffu, q, o);
            if (lane == 0) s.red2[wid] = q;
        } else if (tid < 128) {
            float v = tanhf(s.hrv[tid - 64]); s.kr[tid - 64] = v;
            float q = v * v;
            #pragma unroll
            for (int o = 16; o; o >>= 1) q += __shfl_xor_sync(0xffffffffu, q, o);
            if (lane == 0) s.red2[wid] = q;
        } else if (tid < 192) s.ev[tid - 128] = sigmoidf_(s.hwv[70 + tid - 128]);
        else if (tid < 256) s.av[tid - 192] = tanhf(s.hwv[134 + tid - 192]);
        else if (tid == 256) s.sc[0] = softplusf_(s.hwv[64]);
        else if (tid == 257) s.sc[1] = sigmoidf_(s.hwv[65]);
        else if (tid == 258) {
            float a0 = s.hwv[66], a1 = s.hwv[67], a2 = s.hwv[68];
            float m = fmaxf(a0, fmaxf(a1, a2));
            float e0 = expf(a0 - m), e1 = expf(a1 - m), e2 = expf(a2 - m);
            float z = e0 + e1 + e2;
            s.sc[2] = e0 / z; s.sc[3] = e1 / z; s.sc[4] = e2 / z;
        }
        else if (tid == 259) s.sc[5] = 1.f + softplusf_(s.hwv[69]);
        else if (tid == 260) s.sc[8] = softplusf_(s.hrv[64]);
        else if (tid == 261) s.sc[9] = sigmoidf_(s.hrv[65]);
        else if (tid == 262) {
            float a0 = s.hrv[66], a1 = s.hrv[67], a2 = s.hrv[68];
            float m = fmaxf(a0, fmaxf(a1, a2));
            float e0 = expf(a0 - m), e1 = expf(a1 - m), e2 = expf(a2 - m);
            float z = e0 + e1 + e2;
            s.sc[10] = e0 / z; s.sc[11] = e1 / z; s.sc[12] = e2 / z;
        }
        else if (tid == 263) s.sc[13] = 1.f + softplusf_(s.hrv[69]);
        __syncthreads();

        // ---- Pass A: dot(M, k_w), sumsq reused from prev Pass B ----
        {
            float d0 = 0.f, d1 = 0.f;
            #pragma unroll
            for (int j4 = 0; j4 < 16; ++j4) {
                float4 kk = *(const float4*)(s.kw + 4 * j4);
                d0 += Mreg[4*j4] * kk.x + Mreg[4*j4+1] * kk.y + Mreg[4*j4+2] * kk.z + Mreg[4*j4+3] * kk.w;
                d1 += s.Msm[(4*j4  ) * SMS + tid] * kk.x + s.Msm[(4*j4+1) * SMS + tid] * kk.y
                    + s.Msm[(4*j4+2) * SMS + tid] * kk.z + s.Msm[(4*j4+3) * SMS + tid] * kk.w;
            }
            s.dotb[tid] = d0; s.dotb[512 + tid] = d1;
        }
        __syncthreads();

        // ---- write-head addressing ----
        {
            float knw = sqrtf(s.red2[0] + s.red2[1]);
            addr2(tid, lane, wid, s, s.wcarry, s.ww, knw, s.sc + 0, s.redA, s.redB);
        }

        // ---- Pass B: erase/add + dot(M', k_r) + sumsq ----
        {
            float w0 = s.ww[tid], w1 = s.ww[512 + tid];
            float d0 = 0.f, q0 = 0.f, d1 = 0.f, q1 = 0.f;
            #pragma unroll
            for (int j4 = 0; j4 < 16; ++j4) {
                float4 kk = *(const float4*)(s.kr + 4 * j4);
                float4 ee = *(const float4*)(s.ev + 4 * j4);
                float4 aa = *(const float4*)(s.av + 4 * j4);
                #pragma unroll
                for (int e = 0; e < 4; ++e) {
                    int j = 4 * j4 + e;
                    float ev_ = (e == 0) ? ee.x : (e == 1) ? ee.y : (e == 2) ? ee.z : ee.w;
                    float av_ = (e == 0) ? aa.x : (e == 1) ? aa.y : (e == 2) ? aa.z : aa.w;
                    float kv_ = (e == 0) ? kk.x : (e == 1) ? kk.y : (e == 2) ? kk.z : kk.w;
                    float mr = Mreg[j];
                    mr = mr * (1.f - w0 * ev_) + w0 * av_;
                    Mreg[j] = mr;
                    d0 = fmaf(mr, kv_, d0); q0 = fmaf(mr, mr, q0);
                    float ms = s.Msm[j * SMS + tid];
                    ms = ms * (1.f - w1 * ev_) + w1 * av_;
                    s.Msm[j * SMS + tid] = ms;
                    d1 = fmaf(ms, kv_, d1); q1 = fmaf(ms, ms, q1);
                }
            }
            s.dotb[tid] = d0; s.ssb[tid] = q0;
            s.dotb[512 + tid] = d1; s.ssb[512 + tid] = q1;
        }
        __syncthreads();

        // ---- read-head addressing ----
        {
            float knr = sqrtf(s.red2[2] + s.red2[3]);
            addr2(tid, lane, wid, s, s.ww, s.wcarry, knr, s.sc + 8, s.redB, s.redA);
        }

        // ---- Pass C: r = sum_n w_r[n] * M[n] (warp butterfly) ----
        {
            float wr0 = s.wcarry[tid], wr1 = s.wcarry[512 + tid];
            float A[32];
            bool up = (lane & 16);
            #pragma unroll
            for (int i = 0; i < 32; ++i) {
                float lo = wr0 * Mreg[i]      + wr1 * s.Msm[i * SMS + tid];
                float hi = wr0 * Mreg[i + 32] + wr1 * s.Msm[(i + 32) * SMS + tid];
                float keep = up ? hi : lo;
                float send = up ? lo : hi;
                A[i] = keep + __shfl_xor_sync(0xffffffffu, send, 16);
            }
            #pragma unroll
            for (int o = 8; o >= 1; o >>= 1) {
                int hl = o << 1;
                bool u2 = (lane & o);
                #pragma unroll
                for (int i = 0; i < 16; ++i) {
                    if (i < hl) {
                        float keep = u2 ? A[i + hl] : A[i];
                        float send = u2 ? A[i] : A[i + hl];
                        A[i] = keep + __shfl_xor_sync(0xffffffffu, send, o);
                    }
                }
            }
            s.scratch[wid * 64 + 2 * lane]     = A[0];
            s.scratch[wid * 64 + 2 * lane + 1] = A[1];
        }
        __syncthreads();
        if (tid < 64) {
            float acc = 0.f;
            #pragma unroll
            for (int w = 0; w < 16; ++w) acc += s.scratch[w * 64 + tid];
            s.rv[tid] = acc;
            s.cr[256 + tid] = acc;
        }
        __syncthreads();

        // ---- final FC: 16 out-groups(x4) x 32 K-splits(10) = 512 jobs ----
        {
            const int g = tid & 15, split = tid >> 4;
            const float4* w = (const float4*)(Wf) + g;
            float4 acc = make_float4(0.f, 0.f, 0.f, 0.f);
            #pragma unroll
            for (int jj = 0; jj < 10; ++jj) {
                int j = split * 10 + jj;
                float v = s.cr[j];
                float4 w4 = w[(size_t)j * 16];
                acc.x = fmaf(v, w4.x, acc.x); acc.y = fmaf(v, w4.y, acc.y);
                acc.z = fmaf(v, w4.z, acc.z); acc.w = fmaf(v, w4.w, acc.w);
            }
            *(float4*)(s.scratch + split * 64 + 4 * g) = acc;
        }
        __syncthreads();
        if (tid < 64) {
            float acc = bf[tid];
            #pragma unroll
            for (int k = 0; k < 32; ++k) acc += s.scratch[k * 64 + tid];
            out[((size_t)b * Tt + t) * 64 + tid] = sigmoidf_(acc);
        }
        __syncthreads();
    }
}

extern "C" void kernel_launch(void* const* d_in, const int* in_sizes, int n_in,
                              void* d_out, int out_size) {
    (void)in_sizes; (void)n_in; (void)out_size;
    prep_kernel<<<256, HOUT>>>((const float*)d_in[5], (const float*)d_in[3]);
    cudaFuncSetAttribute(ntm_kernel, cudaFuncAttributeMaxDynamicSharedMemorySize,
                         (int)sizeof(Smem));
    ntm_kernel<<<64, NT, sizeof(Smem)>>>(
        (const float*)d_in[0],   // x
        (const float*)d_in[1],   // Wc
        (const float*)d_in[2],   // bc
        (const float*)d_in[4],   // br
        (const float*)d_in[6],   // bw
        (const float*)d_in[7],   // Wf
        (const float*)d_in[8],   // bf
        (const float*)d_in[9],   // r_bias
        (const float*)d_in[10],  // w_bias
        (const float*)d_in[11],  // M_bias
        (float*)d_out);
}